// round 10
// baseline (speedup 1.0000x reference)
#include <cuda_runtime.h>
#include <math.h>

#define BLOCK   256
#define KNN     16
#define HID     64
#define NPTS    65536
#define NBATCH  4

// Scratch: per-batch xyz in AoS float4 (w unused). 4 * 65536 * 16B = 4 MB.
__device__ float4 g_xyz4[NBATCH * NPTS];

// ---------------- Kernel 1: transpose pos [B,3,N] -> float4 [B,N] ----------------
__global__ __launch_bounds__(256) void transpose_pos_kernel(
    const float* __restrict__ pos, int N)
{
    const int q  = blockIdx.x * 256 + threadIdx.x;    // quad index
    const int i  = q * 4;
    const int bb = i >> 16;                           // N = 65536
    const int n  = i & (NPTS - 1);
    const float* px = pos + (size_t)bb * 3 * N;

    const float4 vx = *reinterpret_cast<const float4*>(px + n);
    const float4 vy = *reinterpret_cast<const float4*>(px + N + n);
    const float4 vz = *reinterpret_cast<const float4*>(px + 2 * N + n);

    float4* o = g_xyz4 + i;
    o[0] = make_float4(vx.x, vy.x, vz.x, 0.0f);
    o[1] = make_float4(vx.y, vy.y, vz.y, 0.0f);
    o[2] = make_float4(vx.z, vy.z, vz.z, 0.0f);
    o[3] = make_float4(vx.w, vy.w, vz.w, 0.0f);
}

// ---------------- Kernel 2: features + matvec, 64-reg sweet spot ----------------
// __launch_bounds__(256, 4): 64 regs -> 4 blocks/SM (32 warps, occ 50%).
__global__ __launch_bounds__(BLOCK, 4) void point_embed_kernel(
    const int*   __restrict__ idx,        // [B,N,K] int32
    const float* __restrict__ dist,       // [B,N,K]
    const float* __restrict__ W,          // [10,64]
    const float* __restrict__ bias,       // [64]
    float* __restrict__ out,              // [B,N,64]
    int N)
{
    // Per-warp private tile: no block-wide barrier anywhere.
    __shared__ float feat_s[BLOCK / 32][10][32];

    const int t = threadIdx.x;
    const int w = t >> 5;
    const int l = t & 31;

    const long long base_pt = (long long)blockIdx.x * BLOCK;   // block inside one batch
    const int bb = (int)(base_pt / N);
    const int n  = (int)(base_pt % N) + t;

    const float4* xb = g_xyz4 + (size_t)bb * N;

    const int*   ip = idx  + ((size_t)bb * N + n) * KNN;
    const float* dp = dist + ((size_t)bb * N + n) * KNN;

    // Front-batch ALL independent loads: 4 idx quads + self + 4 dist quads.
    const int4 j0 = *reinterpret_cast<const int4*>(ip);
    const int4 j1 = *reinterpret_cast<const int4*>(ip + 4);
    const int4 j2 = *reinterpret_cast<const int4*>(ip + 8);
    const int4 j3 = *reinterpret_cast<const int4*>(ip + 12);

    const float4 s = __ldg(xb + n);                 // self point

    const float4 e0 = *reinterpret_cast<const float4*>(dp);
    const float4 e1 = *reinterpret_cast<const float4*>(dp + 4);
    const float4 e2 = *reinterpret_cast<const float4*>(dp + 8);
    const float4 e3 = *reinterpret_cast<const float4*>(dp + 12);

    float md = fmaxf(fmaxf(fmaxf(e0.x, e0.y), fmaxf(e0.z, e0.w)),
               fmaxf(fmaxf(fmaxf(e1.x, e1.y), fmaxf(e1.z, e1.w)),
               fmaxf(fmaxf(fmaxf(e2.x, e2.y), fmaxf(e2.z, e2.w)),
                     fmaxf(fmaxf(e3.x, e3.y), fmaxf(e3.z, e3.w)))));

    float mx = -INFINITY, my = -INFINITY, mz = -INFINITY;
    float nx =  INFINITY, ny =  INFINITY, nz =  INFINITY;

    // Gather chain: 4 quads, indices already resident -> pure LDG stream.
    #pragma unroll
    for (int q = 0; q < 4; q++) {
        const int4 jj = (q == 0) ? j0 : (q == 1) ? j1 : (q == 2) ? j2 : j3;
        const float4 a = __ldg(xb + jj.x);
        const float4 b = __ldg(xb + jj.y);
        const float4 c = __ldg(xb + jj.z);
        const float4 d = __ldg(xb + jj.w);
        mx = fmaxf(fmaxf(fmaxf(mx, a.x), fmaxf(b.x, c.x)), d.x);
        my = fmaxf(fmaxf(fmaxf(my, a.y), fmaxf(b.y, c.y)), d.y);
        mz = fmaxf(fmaxf(fmaxf(mz, a.z), fmaxf(b.z, c.z)), d.z);
        nx = fminf(fminf(fminf(nx, a.x), fminf(b.x, c.x)), d.x);
        ny = fminf(fminf(fminf(ny, a.y), fminf(b.y, c.y)), d.y);
        nz = fminf(fminf(fminf(nz, a.z), fminf(b.z, c.z)), d.z);
    }

    feat_s[w][0][l] = s.x;
    feat_s[w][1][l] = s.y;
    feat_s[w][2][l] = s.z;
    feat_s[w][3][l] = mx;
    feat_s[w][4][l] = my;
    feat_s[w][5][l] = mz;
    feat_s[w][6][l] = s.x - nx;   // max(ext - nbr) = ext - min(nbr)
    feat_s[w][7][l] = s.y - ny;
    feat_s[w][8][l] = s.z - nz;
    feat_s[w][9][l] = md;

    __syncwarp();

    // Phase 2 (per-warp): lane l owns channels {2l, 2l+1}; loop 32 points.
    const float2* W2 = reinterpret_cast<const float2*>(W);     // [10][32] float2
    float2 wc[10];
    #pragma unroll
    for (int c = 0; c < 10; c++) wc[c] = __ldg(W2 + c * 32 + l);
    const float2 bv = __ldg(reinterpret_cast<const float2*>(bias) + l);

    float2* ob = reinterpret_cast<float2*>(out + (base_pt + (long long)w * 32) * HID);

    #pragma unroll 8
    for (int p = 0; p < 32; p++) {
        float2 acc = bv;
        #pragma unroll
        for (int c = 0; c < 10; c++) {
            const float f = feat_s[w][c][p];      // warp broadcast, conflict-free
            acc.x = fmaf(f, wc[c].x, acc.x);
            acc.y = fmaf(f, wc[c].y, acc.y);
        }
        acc.x = fmaxf(acc.x, 0.0f);
        acc.y = fmaxf(acc.y, 0.0f);
        ob[p * 32 + l] = acc;                      // warp writes 256B contiguous
    }
}

extern "C" void kernel_launch(void* const* d_in, const int* in_sizes, int n_in,
                              void* d_out, int out_size) {
    const float* pos  = (const float*)d_in[0];   // [B,3,N] f32
    const int*   idx  = (const int*)d_in[1];     // [B,N,K] i32
    const float* dist = (const float*)d_in[2];   // [B,N,K] f32
    const float* W    = (const float*)d_in[3];   // [10,64] f32
    const float* bias = (const float*)d_in[4];   // [64]    f32
    float*       out  = (float*)d_out;           // [B,N,64] f32

    const int N  = NPTS;
    const long long BN = (long long)out_size / HID;   // B*N total points

    transpose_pos_kernel<<<(int)(BN / 1024), 256>>>(pos, N);
    point_embed_kernel<<<(int)(BN / BLOCK), BLOCK>>>(idx, dist, W, bias, out, N);
}

// round 12
// speedup vs baseline: 1.5698x; 1.5698x over previous
#include <cuda_runtime.h>
#include <cuda_pipeline.h>
#include <math.h>

#define BLOCK   128
#define KNN     16
#define HID     64
#define NPTS    65536
#define NBATCH  4

// Scratch: per-batch xyz in AoS float4 (w unused). 4 * 65536 * 16B = 4 MB.
__device__ float4 g_xyz4[NBATCH * NPTS];

// ---------------- Kernel 1: transpose pos [B,3,N] -> float4 [B,N] ----------------
__global__ __launch_bounds__(256) void transpose_pos_kernel(
    const float* __restrict__ pos, int N)
{
    const int q  = blockIdx.x * 256 + threadIdx.x;    // quad index
    const int i  = q * 4;
    const int bb = i >> 16;                           // N = 65536
    const int n  = i & (NPTS - 1);
    const float* px = pos + (size_t)bb * 3 * N;

    const float4 vx = *reinterpret_cast<const float4*>(px + n);
    const float4 vy = *reinterpret_cast<const float4*>(px + N + n);
    const float4 vz = *reinterpret_cast<const float4*>(px + 2 * N + n);

    float4* o = g_xyz4 + i;
    o[0] = make_float4(vx.x, vy.x, vz.x, 0.0f);
    o[1] = make_float4(vx.y, vy.y, vz.y, 0.0f);
    o[2] = make_float4(vx.z, vy.z, vz.z, 0.0f);
    o[3] = make_float4(vx.w, vy.w, vz.w, 0.0f);
}

// ---------------- Kernel 2: cp.async gather (register-free payload) ----------------
__global__ __launch_bounds__(BLOCK) void point_embed_kernel(
    const int*   __restrict__ idx,        // [B,N,K] int32
    const float* __restrict__ dist,       // [B,N,K]
    const float* __restrict__ W,          // [10,64]
    const float* __restrict__ bias,       // [64]
    float* __restrict__ out,              // [B,N,64]
    int N)
{
    __shared__ float4 gbuf[KNN][BLOCK];               // 32 KB gather staging
    __shared__ float  feat_s[BLOCK / 32][10][32];     // per-warp tiles

    const int t = threadIdx.x;
    const int w = t >> 5;
    const int l = t & 31;

    const long long base_pt = (long long)blockIdx.x * BLOCK;   // block inside one batch
    const int bb = (int)(base_pt / N);
    const int n  = (int)(base_pt % N) + t;

    const float4* xb = g_xyz4 + (size_t)bb * N;

    const int*   ip = idx  + ((size_t)bb * N + n) * KNN;
    const float* dp = dist + ((size_t)bb * N + n) * KNN;

    // Front-load indices (16 regs), then fire ALL 16 gathers via cp.async:
    // payload lands in smem, registers stay free -> 16 in flight per thread.
    const int4 j0 = *reinterpret_cast<const int4*>(ip);
    const int4 j1 = *reinterpret_cast<const int4*>(ip + 4);
    const int4 j2 = *reinterpret_cast<const int4*>(ip + 8);
    const int4 j3 = *reinterpret_cast<const int4*>(ip + 12);

    __pipeline_memcpy_async(&gbuf[ 0][t], xb + j0.x, 16);
    __pipeline_memcpy_async(&gbuf[ 1][t], xb + j0.y, 16);
    __pipeline_memcpy_async(&gbuf[ 2][t], xb + j0.z, 16);
    __pipeline_memcpy_async(&gbuf[ 3][t], xb + j0.w, 16);
    __pipeline_memcpy_async(&gbuf[ 4][t], xb + j1.x, 16);
    __pipeline_memcpy_async(&gbuf[ 5][t], xb + j1.y, 16);
    __pipeline_memcpy_async(&gbuf[ 6][t], xb + j1.z, 16);
    __pipeline_memcpy_async(&gbuf[ 7][t], xb + j1.w, 16);
    __pipeline_memcpy_async(&gbuf[ 8][t], xb + j2.x, 16);
    __pipeline_memcpy_async(&gbuf[ 9][t], xb + j2.y, 16);
    __pipeline_memcpy_async(&gbuf[10][t], xb + j2.z, 16);
    __pipeline_memcpy_async(&gbuf[11][t], xb + j2.w, 16);
    __pipeline_memcpy_async(&gbuf[12][t], xb + j3.x, 16);
    __pipeline_memcpy_async(&gbuf[13][t], xb + j3.y, 16);
    __pipeline_memcpy_async(&gbuf[14][t], xb + j3.z, 16);
    __pipeline_memcpy_async(&gbuf[15][t], xb + j3.w, 16);
    __pipeline_commit();

    // Overlap: self point + dist reduction while gathers are in flight.
    const float4 s = __ldg(xb + n);

    const float4 e0 = *reinterpret_cast<const float4*>(dp);
    const float4 e1 = *reinterpret_cast<const float4*>(dp + 4);
    const float4 e2 = *reinterpret_cast<const float4*>(dp + 8);
    const float4 e3 = *reinterpret_cast<const float4*>(dp + 12);
    const float md = fmaxf(fmaxf(fmaxf(e0.x, e0.y), fmaxf(e0.z, e0.w)),
                     fmaxf(fmaxf(fmaxf(e1.x, e1.y), fmaxf(e1.z, e1.w)),
                     fmaxf(fmaxf(fmaxf(e2.x, e2.y), fmaxf(e2.z, e2.w)),
                           fmaxf(fmaxf(e3.x, e3.y), fmaxf(e3.z, e3.w)))));

    __pipeline_wait_prior(0);

    float mx = -INFINITY, my = -INFINITY, mz = -INFINITY;
    float nx =  INFINITY, ny =  INFINITY, nz =  INFINITY;

    #pragma unroll
    for (int k = 0; k < KNN; k += 4) {
        const float4 a = gbuf[k    ][t];   // LDS.128, 16B lane stride: conflict-free
        const float4 b = gbuf[k + 1][t];
        const float4 c = gbuf[k + 2][t];
        const float4 d = gbuf[k + 3][t];
        mx = fmaxf(fmaxf(fmaxf(mx, a.x), fmaxf(b.x, c.x)), d.x);
        my = fmaxf(fmaxf(fmaxf(my, a.y), fmaxf(b.y, c.y)), d.y);
        mz = fmaxf(fmaxf(fmaxf(mz, a.z), fmaxf(b.z, c.z)), d.z);
        nx = fminf(fminf(fminf(nx, a.x), fminf(b.x, c.x)), d.x);
        ny = fminf(fminf(fminf(ny, a.y), fminf(b.y, c.y)), d.y);
        nz = fminf(fminf(fminf(nz, a.z), fminf(b.z, c.z)), d.z);
    }

    feat_s[w][0][l] = s.x;
    feat_s[w][1][l] = s.y;
    feat_s[w][2][l] = s.z;
    feat_s[w][3][l] = mx;
    feat_s[w][4][l] = my;
    feat_s[w][5][l] = mz;
    feat_s[w][6][l] = s.x - nx;   // max(ext - nbr) = ext - min(nbr)
    feat_s[w][7][l] = s.y - ny;
    feat_s[w][8][l] = s.z - nz;
    feat_s[w][9][l] = md;

    __syncwarp();

    // Phase 2 (per-warp): lane l owns channels {2l, 2l+1}; loop 32 points.
    const float2* W2 = reinterpret_cast<const float2*>(W);     // [10][32] float2
    float2 wc[10];
    #pragma unroll
    for (int c = 0; c < 10; c++) wc[c] = __ldg(W2 + c * 32 + l);
    const float2 bv = __ldg(reinterpret_cast<const float2*>(bias) + l);

    float2* ob = reinterpret_cast<float2*>(out + (base_pt + (long long)w * 32) * HID);

    #pragma unroll 8
    for (int p = 0; p < 32; p++) {
        float2 acc = bv;
        #pragma unroll
        for (int c = 0; c < 10; c++) {
            const float f = feat_s[w][c][p];      // warp broadcast, conflict-free
            acc.x = fmaf(f, wc[c].x, acc.x);
            acc.y = fmaf(f, wc[c].y, acc.y);
        }
        acc.x = fmaxf(acc.x, 0.0f);
        acc.y = fmaxf(acc.y, 0.0f);
        ob[p * 32 + l] = acc;                      // warp writes 256B contiguous
    }
}

extern "C" void kernel_launch(void* const* d_in, const int* in_sizes, int n_in,
                              void* d_out, int out_size) {
    const float* pos  = (const float*)d_in[0];   // [B,3,N] f32
    const int*   idx  = (const int*)d_in[1];     // [B,N,K] i32
    const float* dist = (const float*)d_in[2];   // [B,N,K] f32
    const float* W    = (const float*)d_in[3];   // [10,64] f32
    const float* bias = (const float*)d_in[4];   // [64]    f32
    float*       out  = (float*)d_out;           // [B,N,64] f32

    const int N  = NPTS;
    const long long BN = (long long)out_size / HID;   // B*N total points

    transpose_pos_kernel<<<(int)(BN / 1024), 256>>>(pos, N);
    point_embed_kernel<<<(int)(BN / BLOCK), BLOCK>>>(idx, dist, W, bias, out, N);
}